// round 4
// baseline (speedup 1.0000x reference)
#include <cuda_runtime.h>
#include <math.h>

// ---------------- problem constants ----------------
#define NB      4096
#define LATENT  768
#define COND    512
#define HIDDEN  1024
#define OUTD    512
#define NE      8
#define GATE_H  512
#define INPUT   1280   // LATENT + COND
#define INTER   1792   // LATENT + HIDDEN
#define NEG_SLOPE 0.01f
#define LN_EPS  1e-5f

// ---------------- scratch (device globals; no allocation allowed) -------------
__device__ float g_zc[NB * INPUT];      // concat(z, c)
__device__ float g_g1[NB * GATE_H];     // gate hidden 1
__device__ float g_g2[NB * GATE_H];     // gate hidden 2
__device__ float g_coeff[NB * NE];      // softmax gate coefficients
__device__ float g_x[NB * INTER];       // layernorm output (width 1280 or 1792)
__device__ float g_h[NB * HIDDEN];      // running layer_out

// ---------------- concat(z, c) -> zc ----------------
__global__ void concat_zc_kernel(const float* __restrict__ Z,
                                 const float* __restrict__ C,
                                 float* __restrict__ ZC) {
    int idx = blockIdx.x * blockDim.x + threadIdx.x;   // one float4 per thread
    const int total = NB * INPUT / 4;
    if (idx >= total) return;
    int row  = idx / (INPUT / 4);
    int col4 = idx - row * (INPUT / 4);
    float4 v;
    if (col4 < LATENT / 4)
        v = ((const float4*)Z)[row * (LATENT / 4) + col4];
    else
        v = ((const float4*)C)[row * (COND / 4) + (col4 - LATENT / 4)];
    ((float4*)ZC)[idx] = v;
}

// ---------------- generic SGEMM: C = leaky(A[M,K] @ W[K,N] + bias[N]) ----------
// BM=BN=128, BK=16, 256 threads, 8x8 microtile. M%128==0, N%128==0, K%16==0.
__global__ __launch_bounds__(256, 2)
void sgemm_bias_leaky(const float* __restrict__ A, const float* __restrict__ W,
                      const float* __restrict__ bias, float* __restrict__ C,
                      int K, int N) {
    __shared__ float As[16][132];
    __shared__ float Bs[16][128];
    const int tid  = threadIdx.x;
    const int row0 = blockIdx.y * 128;
    const int col0 = blockIdx.x * 128;
    const int tx   = tid & 15, ty = tid >> 4;
    const int a_m0 = tid >> 2;             // 0..63
    const int a_k0 = (tid & 3) * 4;        // 0,4,8,12
    const int a_m1 = a_m0 + 64;
    const int b_k0 = tid >> 5;             // 0..7
    const int b_n0 = (tid * 4) & 127;

    float acc[8][8];
#pragma unroll
    for (int i = 0; i < 8; i++)
#pragma unroll
        for (int j = 0; j < 8; j++) acc[i][j] = 0.f;

    const float* ar0 = A + (size_t)(row0 + a_m0) * K + a_k0;
    const float* ar1 = A + (size_t)(row0 + a_m1) * K + a_k0;
    const float* wp  = W + (size_t)b_k0 * N + col0 + b_n0;

    for (int k0 = 0; k0 < K; k0 += 16) {
        float4 av0 = *(const float4*)(ar0 + k0);
        float4 av1 = *(const float4*)(ar1 + k0);
        As[a_k0 + 0][a_m0] = av0.x; As[a_k0 + 1][a_m0] = av0.y;
        As[a_k0 + 2][a_m0] = av0.z; As[a_k0 + 3][a_m0] = av0.w;
        As[a_k0 + 0][a_m1] = av1.x; As[a_k0 + 1][a_m1] = av1.y;
        As[a_k0 + 2][a_m1] = av1.z; As[a_k0 + 3][a_m1] = av1.w;
        *(float4*)&Bs[b_k0][b_n0]     = *(const float4*)(wp);
        *(float4*)&Bs[b_k0 + 8][b_n0] = *(const float4*)(wp + (size_t)8 * N);
        wp += (size_t)16 * N;
        __syncthreads();
#pragma unroll
        for (int k = 0; k < 16; k++) {
            float a[8], b[8];
            float4 t;
            t = *(float4*)&As[k][ty * 8];     a[0]=t.x; a[1]=t.y; a[2]=t.z; a[3]=t.w;
            t = *(float4*)&As[k][ty * 8 + 4]; a[4]=t.x; a[5]=t.y; a[6]=t.z; a[7]=t.w;
            t = *(float4*)&Bs[k][tx * 8];     b[0]=t.x; b[1]=t.y; b[2]=t.z; b[3]=t.w;
            t = *(float4*)&Bs[k][tx * 8 + 4]; b[4]=t.x; b[5]=t.y; b[6]=t.z; b[7]=t.w;
#pragma unroll
            for (int i = 0; i < 8; i++)
#pragma unroll
                for (int j = 0; j < 8; j++)
                    acc[i][j] = fmaf(a[i], b[j], acc[i][j]);
        }
        __syncthreads();
    }

#pragma unroll
    for (int i = 0; i < 8; i++) {
        int row = row0 + ty * 8 + i;
#pragma unroll
        for (int j = 0; j < 8; j++) {
            int col = col0 + tx * 8 + j;
            float v = acc[i][j] + bias[col];
            v = v > 0.f ? v : NEG_SLOPE * v;
            C[(size_t)row * N + col] = v;
        }
    }
}

// ---------------- last gate layer + softmax ----------------
// coeff[b,:] = softmax(g2[b,:] @ W2[512,8] + b2)
__global__ void gate2_softmax_kernel(const float* __restrict__ G2,
                                     const float* __restrict__ W2,
                                     const float* __restrict__ b2,
                                     float* __restrict__ coeff) {
    __shared__ float sW[NE * GATE_H];   // transposed: sW[e*512 + i]
    const int tid = threadIdx.x;
    for (int idx = tid; idx < GATE_H * NE; idx += blockDim.x) {
        int i = idx >> 3, e = idx & 7;
        sW[e * GATE_H + i] = W2[idx];
    }
    __syncthreads();
    const int warp = tid >> 5, lane = tid & 31;
    const int row = blockIdx.x * 8 + warp;
    const float* xr = G2 + (size_t)row * GATE_H;
    float s[NE];
#pragma unroll
    for (int e = 0; e < NE; e++) s[e] = 0.f;
    for (int i = lane; i < GATE_H; i += 32) {
        float xv = xr[i];
#pragma unroll
        for (int e = 0; e < NE; e++) s[e] = fmaf(xv, sW[e * GATE_H + i], s[e]);
    }
#pragma unroll
    for (int e = 0; e < NE; e++) {
#pragma unroll
        for (int o = 16; o > 0; o >>= 1)
            s[e] += __shfl_xor_sync(0xffffffffu, s[e], o);
        s[e] += b2[e];
    }
    if (lane == 0) {
        float m = s[0];
#pragma unroll
        for (int e = 1; e < NE; e++) m = fmaxf(m, s[e]);
        float ex[NE], zsum = 0.f;
#pragma unroll
        for (int e = 0; e < NE; e++) { ex[e] = expf(s[e] - m); zsum += ex[e]; }
        float inv = 1.f / zsum;
#pragma unroll
        for (int e = 0; e < NE; e++) coeff[row * NE + e] = ex[e] * inv;
    }
}

// ---------------- LayerNorm over concat(z_row[768], s2_row[w2]) ----------------
__global__ void ln_concat_kernel(const float* __restrict__ Z,
                                 const float* __restrict__ S2, int w2,
                                 const float* __restrict__ gamma,
                                 const float* __restrict__ beta,
                                 float* __restrict__ Xout) {
    const int row = blockIdx.x;
    const int tid = threadIdx.x;   // 256 threads
    const int D = LATENT + w2;
    const float* a = Z + (size_t)row * LATENT;
    const float* b = S2 + (size_t)row * w2;

    float s = 0.f, ss = 0.f;
    for (int i = tid; i < LATENT; i += 256) { float v = a[i]; s += v; ss = fmaf(v, v, ss); }
    for (int i = tid; i < w2;     i += 256) { float v = b[i]; s += v; ss = fmaf(v, v, ss); }

    __shared__ float redS[8], redQ[8];
    __shared__ float sh_mu, sh_rstd;
#pragma unroll
    for (int o = 16; o > 0; o >>= 1) {
        s  += __shfl_xor_sync(0xffffffffu, s, o);
        ss += __shfl_xor_sync(0xffffffffu, ss, o);
    }
    int warp = tid >> 5, lane = tid & 31;
    if (lane == 0) { redS[warp] = s; redQ[warp] = ss; }
    __syncthreads();
    if (tid == 0) {
        float S = 0.f, Q = 0.f;
#pragma unroll
        for (int i = 0; i < 8; i++) { S += redS[i]; Q += redQ[i]; }
        float mu = S / (float)D;
        float var = Q / (float)D - mu * mu;
        sh_mu = mu;
        sh_rstd = rsqrtf(var + LN_EPS);
    }
    __syncthreads();
    const float mu = sh_mu, rstd = sh_rstd;
    float* xo = Xout + (size_t)row * D;
    for (int i = tid; i < LATENT; i += 256)
        xo[i] = (a[i] - mu) * rstd * gamma[i] + beta[i];
    for (int i = tid; i < w2; i += 256)
        xo[LATENT + i] = (b[i] - mu) * rstd * gamma[LATENT + i] + beta[LATENT + i];
}

// ---------------- soft-mixed expert GEMM (flattened over experts) --------------
// pre[b,n] = sum_{e,j} coeff[b,e]*X[b,j]*Wt[e*J+j, n]  + sum_e coeff[b,e]*bias[e,n]
// mode 0: out = leaky(pre); mode 1: out = leaky(prev + pre); mode 2: out = pre
__global__ __launch_bounds__(256, 2)
void mix_gemm(const float* __restrict__ X, int J,
              const float* __restrict__ Wt, const float* __restrict__ bias,
              const float* __restrict__ coeff,
              const float* __restrict__ prev, float* __restrict__ Cout,
              int N, int mode) {
    __shared__ float As[16][132];
    __shared__ float Bs[16][128];
    const int tid  = threadIdx.x;
    const int row0 = blockIdx.y * 128;
    const int col0 = blockIdx.x * 128;
    const int tx   = tid & 15, ty = tid >> 4;
    const int a_m0 = tid >> 2;
    const int a_k0 = (tid & 3) * 4;
    const int a_m1 = a_m0 + 64;
    const int b_k0 = tid >> 5;
    const int b_n0 = (tid * 4) & 127;

    float acc[8][8];
#pragma unroll
    for (int i = 0; i < 8; i++)
#pragma unroll
        for (int j = 0; j < 8; j++) acc[i][j] = 0.f;

    const float* xr0 = X + (size_t)(row0 + a_m0) * J + a_k0;
    const float* xr1 = X + (size_t)(row0 + a_m1) * J + a_k0;
    const float* wp  = Wt + (size_t)b_k0 * N + col0 + b_n0;

    for (int e = 0; e < NE; e++) {
        const float c0 = __ldg(&coeff[(row0 + a_m0) * NE + e]);
        const float c1 = __ldg(&coeff[(row0 + a_m1) * NE + e]);
        for (int j0 = 0; j0 < J; j0 += 16) {
            float4 av0 = *(const float4*)(xr0 + j0);
            float4 av1 = *(const float4*)(xr1 + j0);
            av0.x *= c0; av0.y *= c0; av0.z *= c0; av0.w *= c0;
            av1.x *= c1; av1.y *= c1; av1.z *= c1; av1.w *= c1;
            As[a_k0 + 0][a_m0] = av0.x; As[a_k0 + 1][a_m0] = av0.y;
            As[a_k0 + 2][a_m0] = av0.z; As[a_k0 + 3][a_m0] = av0.w;
            As[a_k0 + 0][a_m1] = av1.x; As[a_k0 + 1][a_m1] = av1.y;
            As[a_k0 + 2][a_m1] = av1.z; As[a_k0 + 3][a_m1] = av1.w;
            *(float4*)&Bs[b_k0][b_n0]     = *(const float4*)(wp);
            *(float4*)&Bs[b_k0 + 8][b_n0] = *(const float4*)(wp + (size_t)8 * N);
            wp += (size_t)16 * N;
            __syncthreads();
#pragma unroll
            for (int k = 0; k < 16; k++) {
                float a[8], b[8];
                float4 t;
                t = *(float4*)&As[k][ty * 8];     a[0]=t.x; a[1]=t.y; a[2]=t.z; a[3]=t.w;
                t = *(float4*)&As[k][ty * 8 + 4]; a[4]=t.x; a[5]=t.y; a[6]=t.z; a[7]=t.w;
                t = *(float4*)&Bs[k][tx * 8];     b[0]=t.x; b[1]=t.y; b[2]=t.z; b[3]=t.w;
                t = *(float4*)&Bs[k][tx * 8 + 4]; b[4]=t.x; b[5]=t.y; b[6]=t.z; b[7]=t.w;
#pragma unroll
                for (int i = 0; i < 8; i++)
#pragma unroll
                    for (int j = 0; j < 8; j++)
                        acc[i][j] = fmaf(a[i], b[j], acc[i][j]);
            }
            __syncthreads();
        }
    }

#pragma unroll
    for (int i = 0; i < 8; i++) {
        int row = row0 + ty * 8 + i;
        float c8[NE];
#pragma unroll
        for (int e = 0; e < NE; e++) c8[e] = coeff[row * NE + e];
#pragma unroll
        for (int j = 0; j < 8; j++) {
            int col = col0 + tx * 8 + j;
            float v = acc[i][j];
#pragma unroll
            for (int e = 0; e < NE; e++)
                v = fmaf(c8[e], bias[e * N + col], v);
            if (mode == 0) {
                v = v > 0.f ? v : NEG_SLOPE * v;
            } else if (mode == 1) {
                v += prev[(size_t)row * N + col];
                v = v > 0.f ? v : NEG_SLOPE * v;
            }
            Cout[(size_t)row * N + col] = v;
        }
    }
}

// ---------------- launch ----------------
extern "C" void kernel_launch(void* const* d_in, const int* in_sizes, int n_in,
                              void* d_out, int out_size) {
    const float* z = (const float*)d_in[0];
    const float* c = (const float*)d_in[1];
    const float *w[5], *bb[5], *lng[5], *lnb[5];

    // Disambiguate input ordering: setup_inputs dict order interleaves
    // (w_i, b_i, ln_g_i, ln_b_i); the reference signature groups all w/b first.
    // In dict order d_in[4] is ln_g0 (1280 elems); in signature order it's w1.
    if (in_sizes[4] == INPUT) {
        for (int i = 0; i < 5; i++) {
            w[i]   = (const float*)d_in[2 + 4 * i];
            bb[i]  = (const float*)d_in[3 + 4 * i];
            lng[i] = (const float*)d_in[4 + 4 * i];
            lnb[i] = (const float*)d_in[5 + 4 * i];
        }
    } else {
        for (int i = 0; i < 5; i++) {
            w[i]  = (const float*)d_in[2 + 2 * i];
            bb[i] = (const float*)d_in[3 + 2 * i];
        }
        for (int i = 0; i < 5; i++) {
            lng[i] = (const float*)d_in[12 + 2 * i];
            lnb[i] = (const float*)d_in[13 + 2 * i];
        }
    }
    const float* gW0 = (const float*)d_in[22];
    const float* gb0 = (const float*)d_in[23];
    const float* gW1 = (const float*)d_in[24];
    const float* gb1 = (const float*)d_in[25];
    const float* gW2 = (const float*)d_in[26];
    const float* gb2 = (const float*)d_in[27];
    float* out = (float*)d_out;

    float *zc, *g1, *g2, *coeff, *x, *h;
    cudaGetSymbolAddress((void**)&zc,    g_zc);
    cudaGetSymbolAddress((void**)&g1,    g_g1);
    cudaGetSymbolAddress((void**)&g2,    g_g2);
    cudaGetSymbolAddress((void**)&coeff, g_coeff);
    cudaGetSymbolAddress((void**)&x,     g_x);
    cudaGetSymbolAddress((void**)&h,     g_h);

    // 1) concat
    concat_zc_kernel<<<(NB * INPUT / 4 + 255) / 256, 256>>>(z, c, zc);

    // 2) gate MLP
    sgemm_bias_leaky<<<dim3(GATE_H / 128, NB / 128), 256>>>(zc, gW0, gb0, g1, INPUT, GATE_H);
    sgemm_bias_leaky<<<dim3(GATE_H / 128, NB / 128), 256>>>(g1, gW1, gb1, g2, GATE_H, GATE_H);
    gate2_softmax_kernel<<<NB / 8, 256>>>(g2, gW2, gb2, coeff);

    // 3) layer 0
    ln_concat_kernel<<<NB, 256>>>(z, c, COND, lng[0], lnb[0], x);
    mix_gemm<<<dim3(HIDDEN / 128, NB / 128), 256>>>(x, INPUT, w[0], bb[0], coeff,
                                                    nullptr, h, HIDDEN, 0);
    // 4) layers 1..3 (residual)
    for (int l = 1; l <= 3; l++) {
        ln_concat_kernel<<<NB, 256>>>(z, h, HIDDEN, lng[l], lnb[l], x);
        mix_gemm<<<dim3(HIDDEN / 128, NB / 128), 256>>>(x, INTER, w[l], bb[l], coeff,
                                                        h, h, HIDDEN, 1);
    }
    // 5) final layer (no residual / activation)
    ln_concat_kernel<<<NB, 256>>>(z, h, HIDDEN, lng[4], lnb[4], x);
    mix_gemm<<<dim3(OUTD / 128, NB / 128), 256>>>(x, INTER, w[4], bb[4], coeff,
                                                  nullptr, out, OUTD, 2);
}

// round 7
// speedup vs baseline: 2.1234x; 2.1234x over previous
#include <cuda_runtime.h>
#include <cuda_bf16.h>
#include <math.h>
#include <stdint.h>

// ---------------- problem constants ----------------
#define NB      4096
#define LATENT  768
#define COND    512
#define HIDDEN  1024
#define OUTD    512
#define NE      8
#define GATE_H  512
#define INPUT   1280   // LATENT + COND
#define INTER   1792   // LATENT + HIDDEN
#define NEG_SLOPE 0.01f
#define LN_EPS  1e-5f

// split-weight totals (elements): 10240*1024 + 3*14336*1024 + 14336*512
#define WSPLIT_TOTAL 61865984

// mix_mma staging
#define STAGE   32768          // AH 8K | AL 8K | WH 8K | WL 8K
#define NSTAGE  4
#define OFF_COEFF 0
#define OFF_BIAS  4096
#define OFF_STAGES 8192
#define MIX_SMEM (OFF_STAGES + NSTAGE * STAGE)   // 139264

// ---------------- scratch (device globals; no allocation allowed) -------------
__device__ float g_zc[NB * INPUT];
__device__ float g_g1[NB * GATE_H];
__device__ float g_g2[NB * GATE_H];
__device__ float g_coeff[NB * NE];
__device__ float g_x[NB * INTER];
__device__ float g_h[NB * HIDDEN];
__device__ __nv_bfloat16 g_whi[WSPLIT_TOTAL];
__device__ __nv_bfloat16 g_wlo[WSPLIT_TOTAL];

// ---------------- asm helpers (all base sm_80+ features; no 'a' gating) -------
__device__ __forceinline__ uint32_t smem_u32(const void* p) {
    uint32_t a;
    asm("{ .reg .u64 t; cvta.to.shared.u64 t, %1; cvt.u32.u64 %0, t; }"
        : "=r"(a) : "l"(p));
    return a;
}

#define CPASYNC16(dst, src) \
    asm volatile("cp.async.cg.shared.global [%0], [%1], 16;" \
                 :: "r"(dst), "l"(src) : "memory")
#define CPCOMMIT() asm volatile("cp.async.commit_group;" ::: "memory")
#define CPWAIT1()  asm volatile("cp.async.wait_group 1;" ::: "memory")

#define LDSM4(r, addr) \
    asm volatile("ldmatrix.sync.aligned.m8n8.x4.shared.b16 {%0,%1,%2,%3}, [%4];" \
                 : "=r"((r)[0]), "=r"((r)[1]), "=r"((r)[2]), "=r"((r)[3]) \
                 : "r"(addr))

#define MMA16816(d, a, b) \
    asm volatile("mma.sync.aligned.m16n8k16.row.col.f32.bf16.bf16.f32 " \
                 "{%0,%1,%2,%3}, {%4,%5,%6,%7}, {%8,%9}, {%0,%1,%2,%3};" \
                 : "+f"((d)[0]), "+f"((d)[1]), "+f"((d)[2]), "+f"((d)[3]) \
                 : "r"((a)[0]), "r"((a)[1]), "r"((a)[2]), "r"((a)[3]), \
                   "r"((b)[0]), "r"((b)[1]))

// swizzled byte offset of 16B chunk c in a 64B row (conflict-free for ldmatrix)
__device__ __forceinline__ uint32_t aoff(int row, int c) {
    return (uint32_t)row * 64u + (uint32_t)((c ^ ((row >> 1) & 3)) << 4);
}

// ---------------- concat(z, c) -> zc ----------------
__global__ void concat_zc_kernel(const float* __restrict__ Z,
                                 const float* __restrict__ C,
                                 float* __restrict__ ZC) {
    int idx = blockIdx.x * blockDim.x + threadIdx.x;
    const int total = NB * INPUT / 4;
    if (idx >= total) return;
    int row  = idx / (INPUT / 4);
    int col4 = idx - row * (INPUT / 4);
    float4 v;
    if (col4 < LATENT / 4)
        v = ((const float4*)Z)[row * (LATENT / 4) + col4];
    else
        v = ((const float4*)C)[row * (COND / 4) + (col4 - LATENT / 4)];
    ((float4*)ZC)[idx] = v;
}

// ---------------- gate SGEMM (fp32 FFMA; small) ----------------
__global__ __launch_bounds__(256, 2)
void sgemm_bias_leaky(const float* __restrict__ A, const float* __restrict__ W,
                      const float* __restrict__ bias, float* __restrict__ C,
                      int K, int N) {
    __shared__ float As[16][132];
    __shared__ float Bs[16][128];
    const int tid  = threadIdx.x;
    const int row0 = blockIdx.y * 128;
    const int col0 = blockIdx.x * 128;
    const int tx   = tid & 15, ty = tid >> 4;
    const int a_m0 = tid >> 2;
    const int a_k0 = (tid & 3) * 4;
    const int a_m1 = a_m0 + 64;
    const int b_k0 = tid >> 5;
    const int b_n0 = (tid * 4) & 127;

    float acc[8][8];
#pragma unroll
    for (int i = 0; i < 8; i++)
#pragma unroll
        for (int j = 0; j < 8; j++) acc[i][j] = 0.f;

    const float* ar0 = A + (size_t)(row0 + a_m0) * K + a_k0;
    const float* ar1 = A + (size_t)(row0 + a_m1) * K + a_k0;
    const float* wp  = W + (size_t)b_k0 * N + col0 + b_n0;

    for (int k0 = 0; k0 < K; k0 += 16) {
        float4 av0 = *(const float4*)(ar0 + k0);
        float4 av1 = *(const float4*)(ar1 + k0);
        As[a_k0 + 0][a_m0] = av0.x; As[a_k0 + 1][a_m0] = av0.y;
        As[a_k0 + 2][a_m0] = av0.z; As[a_k0 + 3][a_m0] = av0.w;
        As[a_k0 + 0][a_m1] = av1.x; As[a_k0 + 1][a_m1] = av1.y;
        As[a_k0 + 2][a_m1] = av1.z; As[a_k0 + 3][a_m1] = av1.w;
        *(float4*)&Bs[b_k0][b_n0]     = *(const float4*)(wp);
        *(float4*)&Bs[b_k0 + 8][b_n0] = *(const float4*)(wp + (size_t)8 * N);
        wp += (size_t)16 * N;
        __syncthreads();
#pragma unroll
        for (int k = 0; k < 16; k++) {
            float a[8], b[8];
            float4 t;
            t = *(float4*)&As[k][ty * 8];     a[0]=t.x; a[1]=t.y; a[2]=t.z; a[3]=t.w;
            t = *(float4*)&As[k][ty * 8 + 4]; a[4]=t.x; a[5]=t.y; a[6]=t.z; a[7]=t.w;
            t = *(float4*)&Bs[k][tx * 8];     b[0]=t.x; b[1]=t.y; b[2]=t.z; b[3]=t.w;
            t = *(float4*)&Bs[k][tx * 8 + 4]; b[4]=t.x; b[5]=t.y; b[6]=t.z; b[7]=t.w;
#pragma unroll
            for (int i = 0; i < 8; i++)
#pragma unroll
                for (int j = 0; j < 8; j++)
                    acc[i][j] = fmaf(a[i], b[j], acc[i][j]);
        }
        __syncthreads();
    }

#pragma unroll
    for (int i = 0; i < 8; i++) {
        int row = row0 + ty * 8 + i;
#pragma unroll
        for (int j = 0; j < 8; j++) {
            int col = col0 + tx * 8 + j;
            float v = acc[i][j] + bias[col];
            v = v > 0.f ? v : NEG_SLOPE * v;
            C[(size_t)row * N + col] = v;
        }
    }
}

// ---------------- last gate layer + softmax ----------------
__global__ void gate2_softmax_kernel(const float* __restrict__ G2,
                                     const float* __restrict__ W2,
                                     const float* __restrict__ b2,
                                     float* __restrict__ coeff) {
    __shared__ float sW[NE * GATE_H];
    const int tid = threadIdx.x;
    for (int idx = tid; idx < GATE_H * NE; idx += blockDim.x) {
        int i = idx >> 3, e = idx & 7;
        sW[e * GATE_H + i] = W2[idx];
    }
    __syncthreads();
    const int warp = tid >> 5, lane = tid & 31;
    const int row = blockIdx.x * 8 + warp;
    const float* xr = G2 + (size_t)row * GATE_H;
    float s[NE];
#pragma unroll
    for (int e = 0; e < NE; e++) s[e] = 0.f;
    for (int i = lane; i < GATE_H; i += 32) {
        float xv = xr[i];
#pragma unroll
        for (int e = 0; e < NE; e++) s[e] = fmaf(xv, sW[e * GATE_H + i], s[e]);
    }
#pragma unroll
    for (int e = 0; e < NE; e++) {
#pragma unroll
        for (int o = 16; o > 0; o >>= 1)
            s[e] += __shfl_xor_sync(0xffffffffu, s[e], o);
        s[e] += b2[e];
    }
    if (lane == 0) {
        float m = s[0];
#pragma unroll
        for (int e = 1; e < NE; e++) m = fmaxf(m, s[e]);
        float ex[NE], zsum = 0.f;
#pragma unroll
        for (int e = 0; e < NE; e++) { ex[e] = expf(s[e] - m); zsum += ex[e]; }
        float inv = 1.f / zsum;
#pragma unroll
        for (int e = 0; e < NE; e++) coeff[row * NE + e] = ex[e] * inv;
    }
}

// ---------------- LayerNorm over concat(z_row[768], s2_row[w2]) ----------------
__global__ void ln_concat_kernel(const float* __restrict__ Z,
                                 const float* __restrict__ S2, int w2,
                                 const float* __restrict__ gamma,
                                 const float* __restrict__ beta,
                                 float* __restrict__ Xout) {
    const int row = blockIdx.x;
    const int tid = threadIdx.x;
    const int D = LATENT + w2;
    const float* a = Z + (size_t)row * LATENT;
    const float* b = S2 + (size_t)row * w2;

    float s = 0.f, ss = 0.f;
    for (int i = tid; i < LATENT; i += 256) { float v = a[i]; s += v; ss = fmaf(v, v, ss); }
    for (int i = tid; i < w2;     i += 256) { float v = b[i]; s += v; ss = fmaf(v, v, ss); }

    __shared__ float redS[8], redQ[8];
    __shared__ float sh_mu, sh_rstd;
#pragma unroll
    for (int o = 16; o > 0; o >>= 1) {
        s  += __shfl_xor_sync(0xffffffffu, s, o);
        ss += __shfl_xor_sync(0xffffffffu, ss, o);
    }
    int warp = tid >> 5, lane = tid & 31;
    if (lane == 0) { redS[warp] = s; redQ[warp] = ss; }
    __syncthreads();
    if (tid == 0) {
        float S = 0.f, Q = 0.f;
#pragma unroll
        for (int i = 0; i < 8; i++) { S += redS[i]; Q += redQ[i]; }
        float mu = S / (float)D;
        float var = Q / (float)D - mu * mu;
        sh_mu = mu;
        sh_rstd = rsqrtf(var + LN_EPS);
    }
    __syncthreads();
    const float mu = sh_mu, rstd = sh_rstd;
    float* xo = Xout + (size_t)row * D;
    for (int i = tid; i < LATENT; i += 256)
        xo[i] = (a[i] - mu) * rstd * gamma[i] + beta[i];
    for (int i = tid; i < w2; i += 256)
        xo[LATENT + i] = (b[i] - mu) * rstd * gamma[LATENT + i] + beta[LATENT + i];
}

// ---------------- weight transpose + bf16 hi/lo split --------------------------
// src w[E, J, N] fp32 -> Whi/Wlo[n][k'=j*8+e] bf16 row-major (Kp = 8*J)
__global__ void wsplit_kernel(const float* __restrict__ W,
                              __nv_bfloat16* __restrict__ Whi,
                              __nv_bfloat16* __restrict__ Wlo,
                              int J, int N) {
    __shared__ float t[8][32][33];
    const int j0 = blockIdx.x * 32;
    const int n0 = blockIdx.y * 32;
    const int tid = threadIdx.x;          // 256 threads
    const int Kp = J * 8;

    for (int k = 0; k < 32; k++) {
        int i = tid + k * 256;
        int e = i >> 10, rem = i & 1023;
        int jj = rem >> 5, nn = rem & 31;
        t[e][jj][nn] = W[(size_t)e * J * N + (size_t)(j0 + jj) * N + n0 + nn];
    }
    __syncthreads();

    const int nn = tid >> 3, g = tid & 7;
    for (int jj = g * 4; jj < g * 4 + 4; jj++) {
        union { unsigned short h[8]; uint4 q; } uh, ul;
#pragma unroll
        for (int e = 0; e < 8; e++) {
            float v = t[e][jj][nn];
            __nv_bfloat16 hh = __float2bfloat16(v);
            __nv_bfloat16 ll = __float2bfloat16(v - __bfloat162float(hh));
            uh.h[e] = *(unsigned short*)&hh;
            ul.h[e] = *(unsigned short*)&ll;
        }
        size_t o = (size_t)(n0 + nn) * Kp + (size_t)(j0 + jj) * 8;
        *(uint4*)(Whi + o) = uh.q;
        *(uint4*)(Wlo + o) = ul.q;
    }
}

// ---------------- mma.sync soft-mixed expert GEMM ------------------------------
// out[b,n] = sum_{j,e} (coeff[b,e] x[b,j]) Wt[n, j*8+e]  (+ mixed bias)
// 3-term bf16 compensation: Ahi*Whi + Ahi*Wlo + Alo*Whi, fp32 accum.
// mode 0: leaky(D+mb); 1: leaky(prev+D+mb); 2: D+mb
__global__ __launch_bounds__(256, 1)
void mix_mma(const float* __restrict__ X, int J,
             const __nv_bfloat16* __restrict__ Whi,
             const __nv_bfloat16* __restrict__ Wlo,
             const float* __restrict__ bias,
             const float* __restrict__ coeff,
             const float* __restrict__ prev, float* __restrict__ Cout,
             int N, int mode) {
    extern __shared__ char smem[];
    const uint32_t sb = smem_u32(smem);
    float* coeffS = (float*)(smem + OFF_COEFF);   // [128][8]
    float* biasS  = (float*)(smem + OFF_BIAS);    // [8][128]
    const int tid  = threadIdx.x;
    const int row0 = blockIdx.y * 128;
    const int col0 = blockIdx.x * 128;
    const int Kp = J * 8;
    const int chunks = J / 4;                     // BK=32 -> 4 j per chunk

    // --- one-time caches ---
    {
        int ci = tid * 4;
        *(float4*)(coeffS + ci) = *(const float4*)(coeff + (size_t)row0 * NE + ci);
        int e = tid >> 5, cl = (tid & 31) * 4;
        *(float4*)(biasS + e * 128 + cl) =
            *(const float4*)(bias + (size_t)e * N + col0 + cl);
    }

    // --- producer roles ---
    const int pm = tid >> 1;            // A row 0..127
    const int ph = tid & 1;             // which j-pair
    float pc[8];
    {
        const float* cr = coeff + (size_t)(row0 + pm) * NE;
#pragma unroll
        for (int e = 0; e < 8; e++) pc[e] = cr[e];
    }
    const float* xrow = X + (size_t)(row0 + pm) * J + ph * 2;
    const int wn = tid >> 1;            // W row (n local)
    const int wc = (tid & 1) * 2;       // chunk pair
    const __nv_bfloat16* whRow = Whi + (size_t)(col0 + wn) * Kp + wc * 8;
    const __nv_bfloat16* wlRow = Wlo + (size_t)(col0 + wn) * Kp + wc * 8;

    // stage filler: A (regs->split->STS) + W (cp.async)
    auto fill = [&](int sidx, float2 a, int kc) {
        const uint32_t soff = OFF_STAGES + (uint32_t)sidx * STAGE;
#pragma unroll
        for (int jj2 = 0; jj2 < 2; jj2++) {
            float xv = jj2 ? a.y : a.x;
            int c = ph * 2 + jj2;
            union { unsigned short h[8]; uint4 q; } uh, ul;
#pragma unroll
            for (int e = 0; e < 8; e++) {
                float p = xv * pc[e];
                __nv_bfloat16 hh = __float2bfloat16(p);
                __nv_bfloat16 ll = __float2bfloat16(p - __bfloat162float(hh));
                uh.h[e] = *(unsigned short*)&hh;
                ul.h[e] = *(unsigned short*)&ll;
            }
            uint32_t off = aoff(pm, c);
            *(uint4*)(smem + soff + off)        = uh.q;
            *(uint4*)(smem + soff + 8192 + off) = ul.q;
        }
        const __nv_bfloat16* sh = whRow + (size_t)kc * 32;
        const __nv_bfloat16* sl = wlRow + (size_t)kc * 32;
#pragma unroll
        for (int q = 0; q < 2; q++) {
            uint32_t off = aoff(wn, wc + q);
            CPASYNC16(sb + soff + 16384 + off, sh + q * 8);
            CPASYNC16(sb + soff + 24576 + off, sl + q * 8);
        }
    };

    float acc[4][4][4];
#pragma unroll
    for (int a = 0; a < 4; a++)
#pragma unroll
        for (int b = 0; b < 4; b++)
#pragma unroll
            for (int c = 0; c < 4; c++) acc[a][b][c] = 0.f;

    // --- prologue: stages 0,1 + A prefetch for 2 ---
    {
        float2 a0 = *(const float2*)(xrow + 0);
        fill(0, a0, 0); CPCOMMIT();
        float2 a1 = *(const float2*)(xrow + 4);
        fill(1, a1, 1); CPCOMMIT();
    }
    float2 aCur = *(const float2*)(xrow + (size_t)(2 < chunks ? 2 : 0) * 4);

    const int wid = tid >> 5, lane = tid & 31;
    const int warp_m = wid & 1, warp_n = wid >> 1;   // 2 x 4 warp grid
    const int arl = lane & 15, ach = lane >> 4;      // A ldmatrix lane roles
    const int bn  = warp_n * 32 + (lane >> 3) * 8 + (lane & 7);  // B lane row

    for (int i = 0; i < chunks; i++) {
        CPWAIT1();
        __syncthreads();
        const uint32_t stg = sb + OFF_STAGES + (uint32_t)(i & 3) * STAGE;
#pragma unroll
        for (int ks = 0; ks < 2; ks++) {
            uint32_t aH[4][4], aL[4][4], bH[4][2], bL[4][2];
#pragma unroll
            for (int mt = 0; mt < 4; mt++) {
                int row = warp_m * 64 + mt * 16 + arl;
                uint32_t off = aoff(row, 2 * ks + ach);
                LDSM4(aH[mt], stg + off);
                LDSM4(aL[mt], stg + 8192 + off);
            }
#pragma unroll
            for (int kh = 0; kh < 2; kh++) {
                uint32_t off = aoff(bn, 2 * ks + kh);
                uint32_t t[4];
                LDSM4(t, stg + 16384 + off);
                bH[0][kh] = t[0]; bH[1][kh] = t[1];
                bH[2][kh] = t[2]; bH[3][kh] = t[3];
                LDSM4(t, stg + 24576 + off);
                bL[0][kh] = t[0]; bL[1][kh] = t[1];
                bL[2][kh] = t[2]; bL[3][kh] = t[3];
            }
#pragma unroll
            for (int mt = 0; mt < 4; mt++)
#pragma unroll
                for (int nt = 0; nt < 4; nt++) {
                    MMA16816(acc[mt][nt], aH[mt], bH[nt]);
                    MMA16816(acc[mt][nt], aH[mt], bL[nt]);
                    MMA16816(acc[mt][nt], aL[mt], bH[nt]);
                }
        }
        // fill stage i+2 (disjoint buffer; overlaps tensor drain)
        if (i + 2 < chunks) fill((i + 2) & 3, aCur, i + 2);
        CPCOMMIT();
        if (i + 3 < chunks) aCur = *(const float2*)(xrow + (size_t)(i + 3) * 4);
    }

    // --- epilogue: bias mix + residual + leaky, direct reg->gmem ---
#pragma unroll
    for (int mt = 0; mt < 4; mt++) {
        int rL0 = warp_m * 64 + mt * 16 + (lane >> 2);
        int rL1 = rL0 + 8;
        float cr0[8], cr1[8];
#pragma unroll
        for (int e = 0; e < 8; e++) {
            cr0[e] = coeffS[rL0 * 8 + e];
            cr1[e] = coeffS[rL1 * 8 + e];
        }
#pragma unroll
        for (int nt = 0; nt < 4; nt++) {
            int cL = warp_n * 32 + nt * 8 + (lane & 3) * 2;
            float m00 = 0.f, m01 = 0.f, m10 = 0.f, m11 = 0.f;
#pragma unroll
            for (int e = 0; e < 8; e++) {
                float b0 = biasS[e * 128 + cL], b1 = biasS[e * 128 + cL + 1];
                m00 = fmaf(cr0[e], b0, m00); m01 = fmaf(cr0[e], b1, m01);
                m10 = fmaf(cr1[e], b0, m10); m11 = fmaf(cr1[e], b1, m11);
            }
            float v00 = acc[mt][nt][0] + m00, v01 = acc[mt][nt][1] + m01;
            float v10 = acc[mt][nt][2] + m10, v11 = acc[mt][nt][3] + m11;
            size_t g0 = (size_t)(row0 + rL0) * N + col0 + cL;
            size_t g1 = (size_t)(row0 + rL1) * N + col0 + cL;
            if (mode == 1) {
                float2 p0 = *(const float2*)(prev + g0);
                float2 p1 = *(const float2*)(prev + g1);
                v00 += p0.x; v01 += p0.y; v10 += p1.x; v11 += p1.y;
            }
            if (mode != 2) {
                v00 = v00 > 0.f ? v00 : NEG_SLOPE * v00;
                v01 = v01 > 0.f ? v01 : NEG_SLOPE * v01;
                v10 = v10 > 0.f ? v10 : NEG_SLOPE * v10;
                v11 = v11 > 0.f ? v11 : NEG_SLOPE * v11;
            }
            *(float2*)(Cout + g0) = make_float2(v00, v01);
            *(float2*)(Cout + g1) = make_float2(v10, v11);
        }
    }
}

// ---------------- launch ----------------
extern "C" void kernel_launch(void* const* d_in, const int* in_sizes, int n_in,
                              void* d_out, int out_size) {
    const float* z = (const float*)d_in[0];
    const float* c = (const float*)d_in[1];
    const float *w[5], *bb[5], *lng[5], *lnb[5];

    if (in_sizes[4] == INPUT) {           // dict order: w,b,ln_g,ln_b interleaved
        for (int i = 0; i < 5; i++) {
            w[i]   = (const float*)d_in[2 + 4 * i];
            bb[i]  = (const float*)d_in[3 + 4 * i];
            lng[i] = (const float*)d_in[4 + 4 * i];
            lnb[i] = (const float*)d_in[5 + 4 * i];
        }
    } else {                              // signature order: all w/b then all ln
        for (int i = 0; i < 5; i++) {
            w[i]  = (const float*)d_in[2 + 2 * i];
            bb[i] = (const float*)d_in[3 + 2 * i];
        }
        for (int i = 0; i < 5; i++) {
            lng[i] = (const float*)d_in[12 + 2 * i];
            lnb[i] = (const float*)d_in[13 + 2 * i];
        }
    }
    const float* gW0 = (const float*)d_in[22];
    const float* gb0 = (const float*)d_in[23];
    const float* gW1 = (const float*)d_in[24];
    const float* gb1 = (const float*)d_in[25];
    const float* gW2 = (const float*)d_in[26];
    const float* gb2 = (const float*)d_in[27];
    float* out = (float*)d_out;

    float *zc, *g1, *g2, *coeff, *x, *h;
    __nv_bfloat16 *whi, *wlo;
    cudaGetSymbolAddress((void**)&zc,    g_zc);
    cudaGetSymbolAddress((void**)&g1,    g_g1);
    cudaGetSymbolAddress((void**)&g2,    g_g2);
    cudaGetSymbolAddress((void**)&coeff, g_coeff);
    cudaGetSymbolAddress((void**)&x,     g_x);
    cudaGetSymbolAddress((void**)&h,     g_h);
    cudaGetSymbolAddress((void**)&whi,   g_whi);
    cudaGetSymbolAddress((void**)&wlo,   g_wlo);

    cudaFuncSetAttribute(mix_mma, cudaFuncAttributeMaxDynamicSharedMemorySize, MIX_SMEM);

    const int  Js[5] = {INPUT, INTER, INTER, INTER, INTER};
    const int  Ns[5] = {HIDDEN, HIDDEN, HIDDEN, HIDDEN, OUTD};
    size_t woff[5];
    woff[0] = 0;
    for (int l = 1; l < 5; l++)
        woff[l] = woff[l - 1] + (size_t)Js[l - 1] * 8 * Ns[l - 1];

    // 0) weight transpose + hi/lo split
    for (int l = 0; l < 5; l++)
        wsplit_kernel<<<dim3(Js[l] / 32, Ns[l] / 32), 256>>>(
            w[l], whi + woff[l], wlo + woff[l], Js[l], Ns[l]);

    // 1) concat
    concat_zc_kernel<<<(NB * INPUT / 4 + 255) / 256, 256>>>(z, c, zc);

    // 2) gate MLP + softmax
    sgemm_bias_leaky<<<dim3(GATE_H / 128, NB / 128), 256>>>(zc, gW0, gb0, g1, INPUT, GATE_H);
    sgemm_bias_leaky<<<dim3(GATE_H / 128, NB / 128), 256>>>(g1, gW1, gb1, g2, GATE_H, GATE_H);
    gate2_softmax_kernel<<<NB / 8, 256>>>(g2, gW2, gb2, coeff);

    // 3) layer 0
    ln_concat_kernel<<<NB, 256>>>(z, c, COND, lng[0], lnb[0], x);
    mix_mma<<<dim3(HIDDEN / 128, NB / 128), 256, MIX_SMEM>>>(
        x, INPUT, whi + woff[0], wlo + woff[0], bb[0], coeff, nullptr, h, HIDDEN, 0);

    // 4) layers 1..3 (residual)
    for (int l = 1; l <= 3; l++) {
        ln_concat_kernel<<<NB, 256>>>(z, h, HIDDEN, lng[l], lnb[l], x);
        mix_mma<<<dim3(HIDDEN / 128, NB / 128), 256, MIX_SMEM>>>(
            x, INTER, whi + woff[l], wlo + woff[l], bb[l], coeff, h, h, HIDDEN, 1);
    }

    // 5) final layer (no residual / activation)
    ln_concat_kernel<<<NB, 256>>>(z, h, HIDDEN, lng[4], lnb[4], x);
    mix_mma<<<dim3(OUTD / 128, NB / 128), 256, MIX_SMEM>>>(
        x, INTER, whi + woff[4], wlo + woff[4], bb[4], coeff, nullptr, out, OUTD, 2);
}